// round 1
// baseline (speedup 1.0000x reference)
#include <cuda_runtime.h>
#include <cuda_bf16.h>
#include <math.h>
#include <float.h>

// ---------------- problem constants ----------------
#define NB      2
#define SEQ     1024
#define TOK     2048          // NB*SEQ
#define DMODEL  1024
#define NH      16
#define NKV     4
#define HDIM    64
#define NEXP    8
#define TOPK    2
#define NLAYER  2
#define VOCAB   32000
#define FFI     3584
#define QKVN    1536          // (NH + 2*NKV)*HDIM
#define NSLOT   (TOK*TOPK)    // 4096

// ---------------- scratch (static device globals; no allocs allowed) ----------------
__device__ float g_x  [TOK*DMODEL];
__device__ float g_xn [TOK*DMODEL];
__device__ float g_qkv[TOK*QKVN];
__device__ float g_y  [TOK*DMODEL];
__device__ float g_h1 [NSLOT*FFI];
__device__ float g_h3 [NSLOT*FFI];
__device__ float g_so [NSLOT*DMODEL];
__device__ int   g_counts[NEXP];
__device__ int   g_offs[NEXP+1];
__device__ int   g_cursor[NEXP];
__device__ int   g_slot_token[NSLOT];
__device__ float g_slot_w[NSLOT];
__device__ int   g_token_slot[NSLOT];
__device__ int   g_tok_e[TOK*TOPK];
__device__ float g_tok_w[TOK*TOPK];

// ---------------- embedding gather ----------------
__global__ void embed_kernel(const int* __restrict__ idx,
                             const float* __restrict__ emb,
                             float* __restrict__ x) {
    int t = blockIdx.x;
    int row = idx[t];
    const float* src = emb + (size_t)row * DMODEL;
    float* dst = x + (size_t)t * DMODEL;
    for (int d = threadIdx.x; d < DMODEL; d += blockDim.x) dst[d] = src[d];
}

// ---------------- rmsnorm ----------------
__global__ __launch_bounds__(256) void rmsnorm_kernel(const float* __restrict__ x,
                                                      const float* __restrict__ w,
                                                      float* __restrict__ o) {
    int t = blockIdx.x;
    const float* xr = x + (size_t)t * DMODEL;
    float ss = 0.f;
    for (int d = threadIdx.x; d < DMODEL; d += 256) { float v = xr[d]; ss += v * v; }
    for (int off = 16; off; off >>= 1) ss += __shfl_xor_sync(0xffffffffu, ss, off);
    __shared__ float red[8];
    __shared__ float s_inv;
    int warp = threadIdx.x >> 5, lane = threadIdx.x & 31;
    if (lane == 0) red[warp] = ss;
    __syncthreads();
    if (threadIdx.x == 0) {
        float tot = 0.f;
        #pragma unroll
        for (int i = 0; i < 8; i++) tot += red[i];
        s_inv = rsqrtf(tot / (float)DMODEL + 1e-5f);
    }
    __syncthreads();
    float inv = s_inv;
    float* op = o + (size_t)t * DMODEL;
    for (int d = threadIdx.x; d < DMODEL; d += 256) op[d] = xr[d] * inv * w[d];
}

// ---------------- RoPE (double-precision tables on the fly) ----------------
__global__ void rope_kernel(float* __restrict__ qkv) {
    int i = blockIdx.x * blockDim.x + threadIdx.x;
    const int total = TOK * (NH + NKV) * (HDIM / 2);
    if (i >= total) return;
    int pair = i & 31;
    int r = i >> 5;
    int head = r % (NH + NKV);
    int t = r / (NH + NKV);
    int s = t & (SEQ - 1);
    double freq = exp((double)pair * (-1.0 / 32.0) * 13.815510557964274); // ln(1e6)
    double ang = (double)s * freq;
    float c = (float)cos(ang), sn = (float)sin(ang);
    float* p = qkv + (size_t)t * QKVN + head * HDIM + 2 * pair;
    float x0 = p[0], x1 = p[1];
    p[0] = x0 * c - x1 * sn;
    p[1] = x1 * c + x0 * sn;
}

// ---------------- plain NT SGEMM: C[M,N] = A[M,K] @ Bw[N,K]^T (+resid) ----------------
// 128x128 tile, BK=8, 256 threads, 8x8 per thread. M%128==0, N%128==0, K%8==0.
template<bool RESID>
__global__ __launch_bounds__(256) void sgemm_nt(const float* __restrict__ A,
                                                const float* __restrict__ Bw,
                                                const float* __restrict__ R,
                                                float* __restrict__ C,
                                                int M, int N, int Kd) {
    __shared__ float As[8][132];
    __shared__ float Bs[8][132];
    const int tid = threadIdx.x;
    const int tx = tid & 15, ty = tid >> 4;
    const int bm = blockIdx.y * 128, bn = blockIdx.x * 128;
    const int arow = tid >> 1, ak = (tid & 1) * 4;
    const float* Ap = A + (size_t)(bm + arow) * Kd + ak;
    const float* Bp = Bw + (size_t)(bn + arow) * Kd + ak;
    float acc[8][8];
    #pragma unroll
    for (int i = 0; i < 8; i++)
        #pragma unroll
        for (int j = 0; j < 8; j++) acc[i][j] = 0.f;

    for (int k0 = 0; k0 < Kd; k0 += 8) {
        float4 av = *reinterpret_cast<const float4*>(Ap + k0);
        float4 bv = *reinterpret_cast<const float4*>(Bp + k0);
        __syncthreads();
        As[ak + 0][arow] = av.x; As[ak + 1][arow] = av.y;
        As[ak + 2][arow] = av.z; As[ak + 3][arow] = av.w;
        Bs[ak + 0][arow] = bv.x; Bs[ak + 1][arow] = bv.y;
        Bs[ak + 2][arow] = bv.z; Bs[ak + 3][arow] = bv.w;
        __syncthreads();
        #pragma unroll
        for (int kk = 0; kk < 8; kk++) {
            float4 a0 = *reinterpret_cast<const float4*>(&As[kk][ty * 4]);
            float4 a1 = *reinterpret_cast<const float4*>(&As[kk][64 + ty * 4]);
            float4 b0 = *reinterpret_cast<const float4*>(&Bs[kk][tx * 4]);
            float4 b1 = *reinterpret_cast<const float4*>(&Bs[kk][64 + tx * 4]);
            float a[8] = {a0.x, a0.y, a0.z, a0.w, a1.x, a1.y, a1.z, a1.w};
            float b[8] = {b0.x, b0.y, b0.z, b0.w, b1.x, b1.y, b1.z, b1.w};
            #pragma unroll
            for (int i = 0; i < 8; i++)
                #pragma unroll
                for (int j = 0; j < 8; j++) acc[i][j] += a[i] * b[j];
        }
    }
    #pragma unroll
    for (int i = 0; i < 8; i++) {
        int r = bm + ((i < 4) ? (ty * 4 + i) : (64 + ty * 4 + i - 4));
        #pragma unroll
        for (int j = 0; j < 8; j++) {
            int c = bn + ((j < 4) ? (tx * 4 + j) : (64 + tx * 4 + j - 4));
            size_t off = (size_t)r * N + c;
            C[off] = RESID ? (acc[i][j] + R[off]) : acc[i][j];
        }
    }
}

// ---------------- MoE grouped SGEMM (per expert, rows = slots) ----------------
// GATHER: A row = X[slot_token[row]]  (pass A).  !GATHER: A row = X[row] (pass B).
// ALPHA : scale output row by slot_w[row] (pass B).
template<bool GATHER, bool ALPHA>
__global__ __launch_bounds__(256) void sgemm_moe(const float* __restrict__ X,
                                                 const float* __restrict__ Wbase,
                                                 long wstride,
                                                 float* __restrict__ C,
                                                 int N, int Kd,
                                                 const int* __restrict__ offs,
                                                 const int* __restrict__ slot_token,
                                                 const float* __restrict__ slot_w) {
    const int e = blockIdx.z;
    const int rbeg = offs[e], rend = offs[e + 1];
    const int row0 = rbeg + blockIdx.y * 128;
    if (row0 >= rend) return;
    const int nrows = min(128, rend - row0);
    const float* W = Wbase + (long)e * wstride;

    __shared__ float As[8][132];
    __shared__ float Bs[8][132];
    const int tid = threadIdx.x;
    const int tx = tid & 15, ty = tid >> 4;
    const int bn = blockIdx.x * 128;
    const int arow = tid >> 1, ak = (tid & 1) * 4;
    int lr = min(arow, nrows - 1);
    int grow = row0 + lr;
    const float* Ap = GATHER ? (X + (size_t)slot_token[grow] * Kd + ak)
                             : (X + (size_t)grow * Kd + ak);
    const float* Bp = W + (size_t)(bn + arow) * Kd + ak;

    float acc[8][8];
    #pragma unroll
    for (int i = 0; i < 8; i++)
        #pragma unroll
        for (int j = 0; j < 8; j++) acc[i][j] = 0.f;

    for (int k0 = 0; k0 < Kd; k0 += 8) {
        float4 av = *reinterpret_cast<const float4*>(Ap + k0);
        float4 bv = *reinterpret_cast<const float4*>(Bp + k0);
        __syncthreads();
        As[ak + 0][arow] = av.x; As[ak + 1][arow] = av.y;
        As[ak + 2][arow] = av.z; As[ak + 3][arow] = av.w;
        Bs[ak + 0][arow] = bv.x; Bs[ak + 1][arow] = bv.y;
        Bs[ak + 2][arow] = bv.z; Bs[ak + 3][arow] = bv.w;
        __syncthreads();
        #pragma unroll
        for (int kk = 0; kk < 8; kk++) {
            float4 a0 = *reinterpret_cast<const float4*>(&As[kk][ty * 4]);
            float4 a1 = *reinterpret_cast<const float4*>(&As[kk][64 + ty * 4]);
            float4 b0 = *reinterpret_cast<const float4*>(&Bs[kk][tx * 4]);
            float4 b1 = *reinterpret_cast<const float4*>(&Bs[kk][64 + tx * 4]);
            float a[8] = {a0.x, a0.y, a0.z, a0.w, a1.x, a1.y, a1.z, a1.w};
            float b[8] = {b0.x, b0.y, b0.z, b0.w, b1.x, b1.y, b1.z, b1.w};
            #pragma unroll
            for (int i = 0; i < 8; i++)
                #pragma unroll
                for (int j = 0; j < 8; j++) acc[i][j] += a[i] * b[j];
        }
    }
    #pragma unroll
    for (int i = 0; i < 8; i++) {
        int lr2 = (i < 4) ? (ty * 4 + i) : (64 + ty * 4 + i - 4);
        if (lr2 >= nrows) continue;
        int gr = row0 + lr2;
        float al = ALPHA ? slot_w[gr] : 1.f;
        #pragma unroll
        for (int j = 0; j < 8; j++) {
            int c = bn + ((j < 4) ? (tx * 4 + j) : (64 + tx * 4 + j - 4));
            C[(size_t)gr * N + c] = al * acc[i][j];
        }
    }
}

// ---------------- flash attention (64x64 tiles, online softmax) ----------------
__global__ __launch_bounds__(256) void flash_kernel(const float* __restrict__ qkv,
                                                    float* __restrict__ y) {
    __shared__ float Qs[64][64];
    __shared__ float Ks[64][64];   // K^T [d][c]; reused as P [r][c]
    __shared__ float Vs[64][64];
    const int b = blockIdx.z, h = blockIdx.y;
    const int q0 = blockIdx.x * 64;
    const int kvh = h >> 2;        // H/KVH = 4
    const int tid = threadIdx.x;
    const int tx = tid & 15, ty = tid >> 4;
    const int lr = tid >> 2;            // 0..63
    const int lc = (tid & 3) * 16;      // 0,16,32,48

    {
        const float* qp = qkv + (size_t)(b * SEQ + q0 + lr) * QKVN + h * HDIM + lc;
        #pragma unroll
        for (int j = 0; j < 4; j++)
            *reinterpret_cast<float4*>(&Qs[lr][lc + j * 4]) =
                *reinterpret_cast<const float4*>(qp + j * 4);
    }

    float m[4], l[4], O[4][4];
    #pragma unroll
    for (int i = 0; i < 4; i++) {
        m[i] = -FLT_MAX; l[i] = 0.f;
        #pragma unroll
        for (int j = 0; j < 4; j++) O[i][j] = 0.f;
    }

    const int ntile = q0 / 64 + 1;
    for (int kt = 0; kt < ntile; kt++) {
        const int k0 = kt * 64;
        __syncthreads();
        {
            const float* kp = qkv + (size_t)(b * SEQ + k0 + lr) * QKVN + DMODEL + kvh * HDIM + lc;
            const float* vp = qkv + (size_t)(b * SEQ + k0 + lr) * QKVN + DMODEL + NKV * HDIM + kvh * HDIM + lc;
            #pragma unroll
            for (int j = 0; j < 4; j++) {
                float4 kv = *reinterpret_cast<const float4*>(kp + j * 4);
                Ks[lc + j * 4 + 0][lr] = kv.x;
                Ks[lc + j * 4 + 1][lr] = kv.y;
                Ks[lc + j * 4 + 2][lr] = kv.z;
                Ks[lc + j * 4 + 3][lr] = kv.w;
                *reinterpret_cast<float4*>(&Vs[lr][lc + j * 4]) =
                    *reinterpret_cast<const float4*>(vp + j * 4);
            }
        }
        __syncthreads();

        float s[4][4];
        #pragma unroll
        for (int i = 0; i < 4; i++)
            #pragma unroll
            for (int j = 0; j < 4; j++) s[i][j] = 0.f;
        for (int d = 0; d < 64; d++) {
            float4 kd = *reinterpret_cast<const float4*>(&Ks[d][tx * 4]);
            #pragma unroll
            for (int i = 0; i < 4; i++) {
                float qv = Qs[ty * 4 + i][d];
                s[i][0] += qv * kd.x; s[i][1] += qv * kd.y;
                s[i][2] += qv * kd.z; s[i][3] += qv * kd.w;
            }
        }

        #pragma unroll
        for (int i = 0; i < 4; i++) {
            int qg = q0 + ty * 4 + i;
            float rm = -FLT_MAX;
            #pragma unroll
            for (int j = 0; j < 4; j++) {
                int kg = k0 + tx * 4 + j;
                float v = (kg <= qg) ? s[i][j] * 0.125f : -FLT_MAX;
                s[i][j] = v;
                rm = fmaxf(rm, v);
            }
            for (int off = 8; off; off >>= 1)
                rm = fmaxf(rm, __shfl_xor_sync(0xffffffffu, rm, off, 16));
            float mn = fmaxf(m[i], rm);
            float corr = __expf(m[i] - mn);
            float rs = 0.f;
            #pragma unroll
            for (int j = 0; j < 4; j++) {
                float p = __expf(s[i][j] - mn);
                s[i][j] = p; rs += p;
            }
            for (int off = 8; off; off >>= 1)
                rs += __shfl_xor_sync(0xffffffffu, rs, off, 16);
            l[i] = l[i] * corr + rs;
            m[i] = mn;
            #pragma unroll
            for (int j = 0; j < 4; j++) O[i][j] *= corr;
        }
        __syncthreads();
        #pragma unroll
        for (int i = 0; i < 4; i++)
            #pragma unroll
            for (int j = 0; j < 4; j++) Ks[ty * 4 + i][tx * 4 + j] = s[i][j];
        __syncthreads();
        for (int c = 0; c < 64; c++) {
            float4 vv = *reinterpret_cast<const float4*>(&Vs[c][tx * 4]);
            #pragma unroll
            for (int i = 0; i < 4; i++) {
                float p = Ks[ty * 4 + i][c];
                O[i][0] += p * vv.x; O[i][1] += p * vv.y;
                O[i][2] += p * vv.z; O[i][3] += p * vv.w;
            }
        }
    }
    #pragma unroll
    for (int i = 0; i < 4; i++) {
        float inv = 1.f / l[i];
        #pragma unroll
        for (int j = 0; j < 4; j++)
            y[(size_t)(b * SEQ + q0 + ty * 4 + i) * DMODEL + h * HDIM + tx * 4 + j] = O[i][j] * inv;
    }
}

// ---------------- MoE routing ----------------
__global__ void zero_counts_kernel(int* counts) {
    if (threadIdx.x < NEXP) counts[threadIdx.x] = 0;
}

__global__ __launch_bounds__(256) void gate_kernel(const float* __restrict__ xn,
                                                   const float* __restrict__ gw,
                                                   int* __restrict__ tok_e,
                                                   float* __restrict__ tok_w,
                                                   int* __restrict__ counts) {
    int t = blockIdx.x;
    int w = threadIdx.x >> 5, lane = threadIdx.x & 31;
    __shared__ float sc[NEXP];
    const float* x = xn + (size_t)t * DMODEL;
    const float* g = gw + (size_t)w * DMODEL;
    float s = 0.f;
    for (int d = lane; d < DMODEL; d += 32) s += x[d] * g[d];
    for (int off = 16; off; off >>= 1) s += __shfl_xor_sync(0xffffffffu, s, off);
    if (lane == 0) sc[w] = s;
    __syncthreads();
    if (threadIdx.x == 0) {
        float mx = sc[0];
        #pragma unroll
        for (int e = 1; e < NEXP; e++) mx = fmaxf(mx, sc[e]);
        float p[NEXP], sum = 0.f;
        #pragma unroll
        for (int e = 0; e < NEXP; e++) { p[e] = __expf(sc[e] - mx); sum += p[e]; }
        int i0 = 0;
        #pragma unroll
        for (int e = 1; e < NEXP; e++) if (p[e] > p[i0]) i0 = e;
        int i1 = (i0 == 0) ? 1 : 0;
        #pragma unroll
        for (int e = 0; e < NEXP; e++) if (e != i0 && p[e] > p[i1]) i1 = e;
        float v0 = p[i0] / sum, v1 = p[i1] / sum;
        float inv = 1.f / (v0 + v1);
        tok_e[2 * t] = i0;  tok_e[2 * t + 1] = i1;
        tok_w[2 * t] = v0 * inv; tok_w[2 * t + 1] = v1 * inv;
        atomicAdd(&counts[i0], 1); atomicAdd(&counts[i1], 1);
    }
}

__global__ void scan_kernel(const int* __restrict__ counts, int* __restrict__ offs,
                            int* __restrict__ cursor) {
    if (threadIdx.x == 0) {
        int acc = 0;
        for (int e = 0; e < NEXP; e++) { offs[e] = acc; cursor[e] = acc; acc += counts[e]; }
        offs[NEXP] = acc;
    }
}

__global__ void scatter_kernel(const int* __restrict__ tok_e, const float* __restrict__ tok_w,
                               int* __restrict__ cursor, int* __restrict__ slot_token,
                               float* __restrict__ slot_w, int* __restrict__ token_slot) {
    int t = blockIdx.x * blockDim.x + threadIdx.x;
    if (t >= TOK) return;
    #pragma unroll
    for (int j = 0; j < TOPK; j++) {
        int e = tok_e[2 * t + j];
        int slot = atomicAdd(&cursor[e], 1);
        slot_token[slot] = t;
        slot_w[slot] = tok_w[2 * t + j];
        token_slot[2 * t + j] = slot;
    }
}

__global__ void silu_mul_kernel(float* __restrict__ h1, const float* __restrict__ h3) {
    long i = (long)blockIdx.x * blockDim.x + threadIdx.x;
    if (i < (long)NSLOT * FFI) {
        float a = h1[i];
        h1[i] = (a / (1.f + __expf(-a))) * h3[i];
    }
}

__global__ void combine_kernel(float* __restrict__ x, const float* __restrict__ so,
                               const int* __restrict__ token_slot) {
    int t = blockIdx.x;
    int s0 = token_slot[2 * t], s1 = token_slot[2 * t + 1];
    float* xp = x + (size_t)t * DMODEL;
    const float* a = so + (size_t)s0 * DMODEL;
    const float* b = so + (size_t)s1 * DMODEL;
    for (int d = threadIdx.x; d < DMODEL; d += blockDim.x) xp[d] += a[d] + b[d];
}

// ---------------- orchestration ----------------
extern "C" void kernel_launch(void* const* d_in, const int* in_sizes, int n_in,
                              void* d_out, int out_size) {
    const int*   idx      = (const int*)  d_in[0];
    const float* tok_emb  = (const float*)d_in[1];
    const float* attn_nw  = (const float*)d_in[2];
    const float* wqkv     = (const float*)d_in[3];
    const float* wo       = (const float*)d_in[4];
    const float* ffn_nw   = (const float*)d_in[5];
    const float* gate_w   = (const float*)d_in[6];
    const float* w1       = (const float*)d_in[7];
    const float* w2       = (const float*)d_in[8];
    const float* w3       = (const float*)d_in[9];
    const float* final_nw = (const float*)d_in[10];
    const float* out_w    = (const float*)d_in[11];
    float* logits = (float*)d_out;

    float *px, *pxn, *pqkv, *py, *ph1, *ph3, *pso, *pslot_w, *ptok_w;
    int *pcounts, *poffs, *pcursor, *pslot_token, *ptoken_slot, *ptok_e;
    cudaGetSymbolAddress((void**)&px, g_x);
    cudaGetSymbolAddress((void**)&pxn, g_xn);
    cudaGetSymbolAddress((void**)&pqkv, g_qkv);
    cudaGetSymbolAddress((void**)&py, g_y);
    cudaGetSymbolAddress((void**)&ph1, g_h1);
    cudaGetSymbolAddress((void**)&ph3, g_h3);
    cudaGetSymbolAddress((void**)&pso, g_so);
    cudaGetSymbolAddress((void**)&pcounts, g_counts);
    cudaGetSymbolAddress((void**)&poffs, g_offs);
    cudaGetSymbolAddress((void**)&pcursor, g_cursor);
    cudaGetSymbolAddress((void**)&pslot_token, g_slot_token);
    cudaGetSymbolAddress((void**)&pslot_w, g_slot_w);
    cudaGetSymbolAddress((void**)&ptoken_slot, g_token_slot);
    cudaGetSymbolAddress((void**)&ptok_e, g_tok_e);
    cudaGetSymbolAddress((void**)&ptok_w, g_tok_w);

    embed_kernel<<<TOK, 256>>>(idx, tok_emb, px);

    for (int l = 0; l < NLAYER; l++) {
        // ---- attention block ----
        rmsnorm_kernel<<<TOK, 256>>>(px, attn_nw + (size_t)l * DMODEL, pxn);
        sgemm_nt<false><<<dim3(QKVN / 128, TOK / 128), 256>>>(
            pxn, wqkv + (size_t)l * QKVN * DMODEL, nullptr, pqkv, TOK, QKVN, DMODEL);
        {
            int total = TOK * (NH + NKV) * (HDIM / 2);
            rope_kernel<<<(total + 255) / 256, 256>>>(pqkv);
        }
        flash_kernel<<<dim3(SEQ / 64, NH, NB), 256>>>(pqkv, py);
        sgemm_nt<true><<<dim3(DMODEL / 128, TOK / 128), 256>>>(
            py, wo + (size_t)l * DMODEL * DMODEL, px, px, TOK, DMODEL, DMODEL);

        // ---- MoE block ----
        rmsnorm_kernel<<<TOK, 256>>>(px, ffn_nw + (size_t)l * DMODEL, pxn);
        zero_counts_kernel<<<1, 32>>>(pcounts);
        gate_kernel<<<TOK, 256>>>(pxn, gate_w + (size_t)l * NEXP * DMODEL,
                                  ptok_e, ptok_w, pcounts);
        scan_kernel<<<1, 1>>>(pcounts, poffs, pcursor);
        scatter_kernel<<<(TOK + 255) / 256, 256>>>(ptok_e, ptok_w, pcursor,
                                                   pslot_token, pslot_w, ptoken_slot);
        sgemm_moe<true, false><<<dim3(FFI / 128, 32, NEXP), 256>>>(
            pxn, w1 + (size_t)l * NEXP * FFI * DMODEL, (long)FFI * DMODEL,
            ph1, FFI, DMODEL, poffs, pslot_token, nullptr);
        sgemm_moe<true, false><<<dim3(FFI / 128, 32, NEXP), 256>>>(
            pxn, w3 + (size_t)l * NEXP * FFI * DMODEL, (long)FFI * DMODEL,
            ph3, FFI, DMODEL, poffs, pslot_token, nullptr);
        {
            long n = (long)NSLOT * FFI;
            silu_mul_kernel<<<(unsigned)((n + 255) / 256), 256>>>(ph1, ph3);
        }
        sgemm_moe<false, true><<<dim3(DMODEL / 128, 32, NEXP), 256>>>(
            ph1, w2 + (size_t)l * NEXP * DMODEL * FFI, (long)DMODEL * FFI,
            pso, DMODEL, FFI, poffs, pslot_token, pslot_w);
        combine_kernel<<<TOK, 256>>>(px, pso, ptoken_slot);
    }

    // ---- final norm + LM head ----
    rmsnorm_kernel<<<TOK, 256>>>(px, final_nw, pxn);
    sgemm_nt<false><<<dim3(VOCAB / 128, TOK / 128), 256>>>(
        pxn, out_w, nullptr, logits, TOK, VOCAB, DMODEL);
}

// round 2
// speedup vs baseline: 2.0651x; 2.0651x over previous
#include <cuda_runtime.h>
#include <cuda_bf16.h>
#include <mma.h>
#include <math.h>
#include <float.h>

using namespace nvcuda;

// ---------------- problem constants ----------------
#define NB      2
#define SEQ     1024
#define TOK     2048          // NB*SEQ
#define DMODEL  1024
#define NH      16
#define NKV     4
#define HDIM    64
#define NEXP    8
#define TOPK    2
#define NLAYER  2
#define VOCAB   32000
#define FFI     3584
#define QKVN    1536          // (NH + 2*NKV)*HDIM
#define NSLOT   (TOK*TOPK)    // 4096
#define NSLOTP  (NSLOT + NEXP*128)   // 5120: per-expert ranges padded to 128

#define BK  32
#define BKP 40                // smem row stride (elements): 80B -> conflict-free ldmatrix

// ---------------- scratch ----------------
__device__ float g_x  [TOK*DMODEL];
__device__ float g_xn [TOK*DMODEL];
__device__ float g_qkv[TOK*QKVN];
__device__ float g_y  [TOK*DMODEL];
__device__ float g_h1 [NSLOTP*FFI];
__device__ float g_h3 [NSLOTP*FFI];
__device__ float g_so [NSLOTP*DMODEL];
__device__ int   g_counts[NEXP];
__device__ int   g_offs[NEXP+1];
__device__ int   g_cursor[NEXP];
__device__ int   g_slot_token[NSLOTP];
__device__ float g_slot_w[NSLOTP];
__device__ int   g_token_slot[NSLOT];
__device__ int   g_tok_e[TOK*TOPK];
__device__ float g_tok_w[TOK*TOPK];

// ---------------- embedding gather ----------------
__global__ void embed_kernel(const int* __restrict__ idx,
                             const float* __restrict__ emb,
                             float* __restrict__ x) {
    int t = blockIdx.x;
    int row = idx[t];
    const float* src = emb + (size_t)row * DMODEL;
    float* dst = x + (size_t)t * DMODEL;
    for (int d = threadIdx.x; d < DMODEL; d += blockDim.x) dst[d] = src[d];
}

// ---------------- rmsnorm ----------------
__global__ __launch_bounds__(256) void rmsnorm_kernel(const float* __restrict__ x,
                                                      const float* __restrict__ w,
                                                      float* __restrict__ o) {
    int t = blockIdx.x;
    const float* xr = x + (size_t)t * DMODEL;
    float ss = 0.f;
    for (int d = threadIdx.x; d < DMODEL; d += 256) { float v = xr[d]; ss += v * v; }
    for (int off = 16; off; off >>= 1) ss += __shfl_xor_sync(0xffffffffu, ss, off);
    __shared__ float red[8];
    __shared__ float s_inv;
    int warp = threadIdx.x >> 5, lane = threadIdx.x & 31;
    if (lane == 0) red[warp] = ss;
    __syncthreads();
    if (threadIdx.x == 0) {
        float tot = 0.f;
        #pragma unroll
        for (int i = 0; i < 8; i++) tot += red[i];
        s_inv = rsqrtf(tot / (float)DMODEL + 1e-5f);
    }
    __syncthreads();
    float inv = s_inv;
    float* op = o + (size_t)t * DMODEL;
    for (int d = threadIdx.x; d < DMODEL; d += 256) op[d] = xr[d] * inv * w[d];
}

// ---------------- RoPE (fp32, matches fp32 reference) ----------------
__global__ void rope_kernel(float* __restrict__ qkv) {
    int i = blockIdx.x * blockDim.x + threadIdx.x;
    const int total = TOK * (NH + NKV) * (HDIM / 2);
    if (i >= total) return;
    int pair = i & 31;
    int r = i >> 5;
    int head = r % (NH + NKV);
    int t = r / (NH + NKV);
    int s = t & (SEQ - 1);
    float freq = expf((float)pair * -0.43173470493638357f); // ln(1e6)/32
    float ang = (float)s * freq;
    float sn, c;
    sincosf(ang, &sn, &c);
    float* p = qkv + (size_t)t * QKVN + head * HDIM + 2 * pair;
    float x0 = p[0], x1 = p[1];
    p[0] = x0 * c - x1 * sn;
    p[1] = x1 * c + x0 * sn;
}

// ---------------- split-float helpers ----------------
__device__ __forceinline__ void split4(const float f[4], __nv_bfloat16* hi, __nv_bfloat16* lo) {
    #pragma unroll
    for (int q = 0; q < 4; q++) {
        __nv_bfloat16 h = __float2bfloat16(f[q]);
        hi[q] = h;
        lo[q] = __float2bfloat16(f[q] - __bfloat162float(h));
    }
}

// ---------------- bf16-split tensor-core GEMM: C[M,N] = A[M,K] @ Bw[N,K]^T (+R) ----------------
// 128x128 tile, BK=32, 256 thr (8 warps as 2Mx4N, warp tile 64x32).
template<bool RESID>
__global__ __launch_bounds__(256) void gemm_bf16_nt(const float* __restrict__ A,
                                                    const float* __restrict__ Bw,
                                                    const float* __restrict__ R,
                                                    float* __restrict__ C,
                                                    int N, int K) {
    __shared__ __nv_bfloat16 Ah[128][BKP], Al[128][BKP], Bh[128][BKP], Bl[128][BKP];
    const int tid = threadIdx.x;
    const int bm = blockIdx.y * 128, bn = blockIdx.x * 128;
    const int lrow = tid >> 3;        // 0..31
    const int lcol = (tid & 7) * 4;   // 0..28
    const int wid = tid >> 5;
    const int wm = (wid & 1) * 64;
    const int wn = (wid >> 1) * 32;

    wmma::fragment<wmma::accumulator, 16, 16, 16, float> acc[4][2];
    #pragma unroll
    for (int i = 0; i < 4; i++)
        #pragma unroll
        for (int j = 0; j < 2; j++) {
            if (RESID)
                wmma::load_matrix_sync(acc[i][j],
                    R + (size_t)(bm + wm + i * 16) * N + bn + wn + j * 16, N, wmma::mem_row_major);
            else
                wmma::fill_fragment(acc[i][j], 0.f);
        }

    for (int k0 = 0; k0 < K; k0 += BK) {
        float4 va[4], vb[4];
        #pragma unroll
        for (int r = 0; r < 4; r++) {
            va[r] = *reinterpret_cast<const float4*>(A + (size_t)(bm + r * 32 + lrow) * K + k0 + lcol);
            vb[r] = *reinterpret_cast<const float4*>(Bw + (size_t)(bn + r * 32 + lrow) * K + k0 + lcol);
        }
        __syncthreads();
        #pragma unroll
        for (int r = 0; r < 4; r++) {
            int row = r * 32 + lrow;
            float fa[4] = {va[r].x, va[r].y, va[r].z, va[r].w};
            float fb[4] = {vb[r].x, vb[r].y, vb[r].z, vb[r].w};
            split4(fa, &Ah[row][lcol], &Al[row][lcol]);
            split4(fb, &Bh[row][lcol], &Bl[row][lcol]);
        }
        __syncthreads();
        #pragma unroll
        for (int ks = 0; ks < BK; ks += 16) {
            wmma::fragment<wmma::matrix_a, 16, 16, 16, __nv_bfloat16, wmma::row_major> ah[4], al[4];
            #pragma unroll
            for (int i = 0; i < 4; i++) {
                wmma::load_matrix_sync(ah[i], &Ah[wm + i * 16][ks], BKP);
                wmma::load_matrix_sync(al[i], &Al[wm + i * 16][ks], BKP);
            }
            #pragma unroll
            for (int j = 0; j < 2; j++) {
                wmma::fragment<wmma::matrix_b, 16, 16, 16, __nv_bfloat16, wmma::col_major> bf;
                wmma::load_matrix_sync(bf, &Bh[wn + j * 16][ks], BKP);
                #pragma unroll
                for (int i = 0; i < 4; i++) wmma::mma_sync(acc[i][j], ah[i], bf, acc[i][j]);
                #pragma unroll
                for (int i = 0; i < 4; i++) wmma::mma_sync(acc[i][j], al[i], bf, acc[i][j]);
                wmma::load_matrix_sync(bf, &Bl[wn + j * 16][ks], BKP);
                #pragma unroll
                for (int i = 0; i < 4; i++) wmma::mma_sync(acc[i][j], ah[i], bf, acc[i][j]);
            }
        }
    }
    #pragma unroll
    for (int i = 0; i < 4; i++)
        #pragma unroll
        for (int j = 0; j < 2; j++)
            wmma::store_matrix_sync(C + (size_t)(bm + wm + i * 16) * N + bn + wn + j * 16,
                                    acc[i][j], N, wmma::mem_row_major);
}

// ---------------- MoE grouped bf16-split GEMM (padded expert ranges: full tiles) ----------------
// GATHER: A row = X[slot_token[row]].  SCALE: A row = X[row] * slot_w[row].
template<bool GATHER, bool SCALE>
__global__ __launch_bounds__(256) void gemm_bf16_moe(const float* __restrict__ X,
                                                     const float* __restrict__ Wbase,
                                                     long wstride,
                                                     float* __restrict__ C,
                                                     int N, int K,
                                                     const int* __restrict__ offs,
                                                     const int* __restrict__ slot_token,
                                                     const float* __restrict__ slot_w) {
    const int e = blockIdx.z;
    const int row0 = offs[e] + blockIdx.y * 128;
    if (row0 >= offs[e + 1]) return;
    const float* W = Wbase + (long)e * wstride;

    __shared__ __nv_bfloat16 Ah[128][BKP], Al[128][BKP], Bh[128][BKP], Bl[128][BKP];
    const int tid = threadIdx.x;
    const int bn = blockIdx.x * 128;
    const int lrow = tid >> 3;
    const int lcol = (tid & 7) * 4;
    const int wid = tid >> 5;
    const int wm = (wid & 1) * 64;
    const int wn = (wid >> 1) * 32;

    const float* aptr[4];
    float ascale[4];
    #pragma unroll
    for (int r = 0; r < 4; r++) {
        int grow = row0 + r * 32 + lrow;
        if (GATHER) {
            aptr[r] = X + (size_t)slot_token[grow] * K;
            ascale[r] = 1.f;
        } else {
            aptr[r] = X + (size_t)grow * K;
            ascale[r] = SCALE ? slot_w[grow] : 1.f;
        }
    }

    wmma::fragment<wmma::accumulator, 16, 16, 16, float> acc[4][2];
    #pragma unroll
    for (int i = 0; i < 4; i++)
        #pragma unroll
        for (int j = 0; j < 2; j++) wmma::fill_fragment(acc[i][j], 0.f);

    for (int k0 = 0; k0 < K; k0 += BK) {
        float4 va[4], vb[4];
        #pragma unroll
        for (int r = 0; r < 4; r++) {
            va[r] = *reinterpret_cast<const float4*>(aptr[r] + k0 + lcol);
            vb[r] = *reinterpret_cast<const float4*>(W + (size_t)(bn + r * 32 + lrow) * K + k0 + lcol);
        }
        __syncthreads();
        #pragma unroll
        for (int r = 0; r < 4; r++) {
            int row = r * 32 + lrow;
            float fa[4] = {va[r].x * ascale[r], va[r].y * ascale[r], va[r].z * ascale[r], va[r].w * ascale[r]};
            float fb[4] = {vb[r].x, vb[r].y, vb[r].z, vb[r].w};
            split4(fa, &Ah[row][lcol], &Al[row][lcol]);
            split4(fb, &Bh[row][lcol], &Bl[row][lcol]);
        }
        __syncthreads();
        #pragma unroll
        for (int ks = 0; ks < BK; ks += 16) {
            wmma::fragment<wmma::matrix_a, 16, 16, 16, __nv_bfloat16, wmma::row_major> ah[4], al[4];
            #pragma unroll
            for (int i = 0; i < 4; i++) {
                wmma::load_matrix_sync(ah[i], &Ah[wm + i * 16][ks], BKP);
                wmma::load_matrix_sync(al[i], &Al[wm + i * 16][ks], BKP);
            }
            #pragma unroll
            for (int j = 0; j < 2; j++) {
                wmma::fragment<wmma::matrix_b, 16, 16, 16, __nv_bfloat16, wmma::col_major> bf;
                wmma::load_matrix_sync(bf, &Bh[wn + j * 16][ks], BKP);
                #pragma unroll
                for (int i = 0; i < 4; i++) wmma::mma_sync(acc[i][j], ah[i], bf, acc[i][j]);
                #pragma unroll
                for (int i = 0; i < 4; i++) wmma::mma_sync(acc[i][j], al[i], bf, acc[i][j]);
                wmma::load_matrix_sync(bf, &Bl[wn + j * 16][ks], BKP);
                #pragma unroll
                for (int i = 0; i < 4; i++) wmma::mma_sync(acc[i][j], ah[i], bf, acc[i][j]);
            }
        }
    }
    #pragma unroll
    for (int i = 0; i < 4; i++)
        #pragma unroll
        for (int j = 0; j < 2; j++)
            wmma::store_matrix_sync(C + (size_t)(row0 + wm + i * 16) * N + bn + wn + j * 16,
                                    acc[i][j], N, wmma::mem_row_major);
}

// ---------------- flash attention (fp32, 64x64 tiles) ----------------
__global__ __launch_bounds__(256) void flash_kernel(const float* __restrict__ qkv,
                                                    float* __restrict__ y) {
    __shared__ float Qs[64][64];
    __shared__ float Ks[64][64];
    __shared__ float Vs[64][64];
    const int b = blockIdx.z, h = blockIdx.y;
    const int q0 = blockIdx.x * 64;
    const int kvh = h >> 2;
    const int tid = threadIdx.x;
    const int tx = tid & 15, ty = tid >> 4;
    const int lr = tid >> 2;
    const int lc = (tid & 3) * 16;

    {
        const float* qp = qkv + (size_t)(b * SEQ + q0 + lr) * QKVN + h * HDIM + lc;
        #pragma unroll
        for (int j = 0; j < 4; j++)
            *reinterpret_cast<float4*>(&Qs[lr][lc + j * 4]) =
                *reinterpret_cast<const float4*>(qp + j * 4);
    }

    float m[4], l[4], O[4][4];
    #pragma unroll
    for (int i = 0; i < 4; i++) {
        m[i] = -FLT_MAX; l[i] = 0.f;
        #pragma unroll
        for (int j = 0; j < 4; j++) O[i][j] = 0.f;
    }

    const int ntile = q0 / 64 + 1;
    for (int kt = 0; kt < ntile; kt++) {
        const int k0 = kt * 64;
        __syncthreads();
        {
            const float* kp = qkv + (size_t)(b * SEQ + k0 + lr) * QKVN + DMODEL + kvh * HDIM + lc;
            const float* vp = qkv + (size_t)(b * SEQ + k0 + lr) * QKVN + DMODEL + NKV * HDIM + kvh * HDIM + lc;
            #pragma unroll
            for (int j = 0; j < 4; j++) {
                float4 kv = *reinterpret_cast<const float4*>(kp + j * 4);
                Ks[lc + j * 4 + 0][lr] = kv.x;
                Ks[lc + j * 4 + 1][lr] = kv.y;
                Ks[lc + j * 4 + 2][lr] = kv.z;
                Ks[lc + j * 4 + 3][lr] = kv.w;
                *reinterpret_cast<float4*>(&Vs[lr][lc + j * 4]) =
                    *reinterpret_cast<const float4*>(vp + j * 4);
            }
        }
        __syncthreads();

        float s[4][4];
        #pragma unroll
        for (int i = 0; i < 4; i++)
            #pragma unroll
            for (int j = 0; j < 4; j++) s[i][j] = 0.f;
        for (int d = 0; d < 64; d++) {
            float4 kd = *reinterpret_cast<const float4*>(&Ks[d][tx * 4]);
            #pragma unroll
            for (int i = 0; i < 4; i++) {
                float qv = Qs[ty * 4 + i][d];
                s[i][0] += qv * kd.x; s[i][1] += qv * kd.y;
                s[i][2] += qv * kd.z; s[i][3] += qv * kd.w;
            }
        }

        #pragma unroll
        for (int i = 0; i < 4; i++) {
            int qg = q0 + ty * 4 + i;
            float rm = -FLT_MAX;
            #pragma unroll
            for (int j = 0; j < 4; j++) {
                int kg = k0 + tx * 4 + j;
                float v = (kg <= qg) ? s[i][j] * 0.125f : -FLT_MAX;
                s[i][j] = v;
                rm = fmaxf(rm, v);
            }
            for (int off = 8; off; off >>= 1)
                rm = fmaxf(rm, __shfl_xor_sync(0xffffffffu, rm, off, 16));
            float mn = fmaxf(m[i], rm);
            float corr = __expf(m[i] - mn);
            float rs = 0.f;
            #pragma unroll
            for (int j = 0; j < 4; j++) {
                float p = __expf(s[i][j] - mn);
                s[i][j] = p; rs += p;
            }
            for (int off = 8; off; off >>= 1)
                rs += __shfl_xor_sync(0xffffffffu, rs, off, 16);
            l[i] = l[i] * corr + rs;
            m[i] = mn;
            #pragma unroll
            for (int j = 0; j < 4; j++) O[i][j] *= corr;
        }
        __syncthreads();
        #pragma unroll
        for (int i = 0; i < 4; i++)
            #pragma unroll
            for (int j = 0; j < 4; j++) Ks[ty * 4 + i][tx * 4 + j] = s[i][j];
        __syncthreads();
        for (int c = 0; c < 64; c++) {
            float4 vv = *reinterpret_cast<const float4*>(&Vs[c][tx * 4]);
            #pragma unroll
            for (int i = 0; i < 4; i++) {
                float p = Ks[ty * 4 + i][c];
                O[i][0] += p * vv.x; O[i][1] += p * vv.y;
                O[i][2] += p * vv.z; O[i][3] += p * vv.w;
            }
        }
    }
    #pragma unroll
    for (int i = 0; i < 4; i++) {
        float inv = 1.f / l[i];
        #pragma unroll
        for (int j = 0; j < 4; j++)
            y[(size_t)(b * SEQ + q0 + ty * 4 + i) * DMODEL + h * HDIM + tx * 4 + j] = O[i][j] * inv;
    }
}

// ---------------- MoE routing ----------------
__global__ void zero_counts_kernel(int* counts) {
    if (threadIdx.x < NEXP) counts[threadIdx.x] = 0;
}

__global__ void init_slots_kernel(int* slot_token, float* slot_w) {
    int i = blockIdx.x * blockDim.x + threadIdx.x;
    if (i < NSLOTP) { slot_token[i] = 0; slot_w[i] = 0.f; }
}

__global__ __launch_bounds__(256) void gate_kernel(const float* __restrict__ xn,
                                                   const float* __restrict__ gw,
                                                   int* __restrict__ tok_e,
                                                   float* __restrict__ tok_w,
                                                   int* __restrict__ counts) {
    int t = blockIdx.x;
    int w = threadIdx.x >> 5, lane = threadIdx.x & 31;
    __shared__ float sc[NEXP];
    const float* x = xn + (size_t)t * DMODEL;
    const float* g = gw + (size_t)w * DMODEL;
    float s = 0.f;
    for (int d = lane; d < DMODEL; d += 32) s += x[d] * g[d];
    for (int off = 16; off; off >>= 1) s += __shfl_xor_sync(0xffffffffu, s, off);
    if (lane == 0) sc[w] = s;
    __syncthreads();
    if (threadIdx.x == 0) {
        float mx = sc[0];
        #pragma unroll
        for (int e = 1; e < NEXP; e++) mx = fmaxf(mx, sc[e]);
        float p[NEXP], sum = 0.f;
        #pragma unroll
        for (int e = 0; e < NEXP; e++) { p[e] = __expf(sc[e] - mx); sum += p[e]; }
        int i0 = 0;
        #pragma unroll
        for (int e = 1; e < NEXP; e++) if (p[e] > p[i0]) i0 = e;
        int i1 = (i0 == 0) ? 1 : 0;
        #pragma unroll
        for (int e = 0; e < NEXP; e++) if (e != i0 && p[e] > p[i1]) i1 = e;
        float v0 = p[i0] / sum, v1 = p[i1] / sum;
        float inv = 1.f / (v0 + v1);
        tok_e[2 * t] = i0;  tok_e[2 * t + 1] = i1;
        tok_w[2 * t] = v0 * inv; tok_w[2 * t + 1] = v1 * inv;
        atomicAdd(&counts[i0], 1); atomicAdd(&counts[i1], 1);
    }
}

__global__ void scan_kernel(const int* __restrict__ counts, int* __restrict__ offs,
                            int* __restrict__ cursor) {
    if (threadIdx.x == 0) {
        int acc = 0;
        for (int e = 0; e < NEXP; e++) {
            offs[e] = acc; cursor[e] = acc;
            acc += ((counts[e] + 127) >> 7) << 7;   // pad to multiple of 128
        }
        offs[NEXP] = acc;
    }
}

__global__ void scatter_kernel(const int* __restrict__ tok_e, const float* __restrict__ tok_w,
                               int* __restrict__ cursor, int* __restrict__ slot_token,
                               float* __restrict__ slot_w, int* __restrict__ token_slot) {
    int t = blockIdx.x * blockDim.x + threadIdx.x;
    if (t >= TOK) return;
    #pragma unroll
    for (int j = 0; j < TOPK; j++) {
        int e = tok_e[2 * t + j];
        int slot = atomicAdd(&cursor[e], 1);
        slot_token[slot] = t;
        slot_w[slot] = tok_w[2 * t + j];
        token_slot[2 * t + j] = slot;
    }
}

__global__ void silu_mul_kernel(float* __restrict__ h1, const float* __restrict__ h3) {
    long i = (long)blockIdx.x * blockDim.x + threadIdx.x;
    if (i < (long)NSLOTP * FFI) {
        float a = h1[i];
        h1[i] = (a / (1.f + __expf(-a))) * h3[i];
    }
}

__global__ void combine_kernel(float* __restrict__ x, const float* __restrict__ so,
                               const int* __restrict__ token_slot) {
    int t = blockIdx.x;
    int s0 = token_slot[2 * t], s1 = token_slot[2 * t + 1];
    float* xp = x + (size_t)t * DMODEL;
    const float* a = so + (size_t)s0 * DMODEL;
    const float* b = so + (size_t)s1 * DMODEL;
    for (int d = threadIdx.x; d < DMODEL; d += blockDim.x) xp[d] += a[d] + b[d];
}

// ---------------- orchestration ----------------
extern "C" void kernel_launch(void* const* d_in, const int* in_sizes, int n_in,
                              void* d_out, int out_size) {
    const int*   idx      = (const int*)  d_in[0];
    const float* tok_emb  = (const float*)d_in[1];
    const float* attn_nw  = (const float*)d_in[2];
    const float* wqkv     = (const float*)d_in[3];
    const float* wo       = (const float*)d_in[4];
    const float* ffn_nw   = (const float*)d_in[5];
    const float* gate_w   = (const float*)d_in[6];
    const float* w1       = (const float*)d_in[7];
    const float* w2       = (const float*)d_in[8];
    const float* w3       = (const float*)d_in[9];
    const float* final_nw = (const float*)d_in[10];
    const float* out_w    = (const float*)d_in[11];
    float* logits = (float*)d_out;

    float *px, *pxn, *pqkv, *py, *ph1, *ph3, *pso, *pslot_w, *ptok_w;
    int *pcounts, *poffs, *pcursor, *pslot_token, *ptoken_slot, *ptok_e;
    cudaGetSymbolAddress((void**)&px, g_x);
    cudaGetSymbolAddress((void**)&pxn, g_xn);
    cudaGetSymbolAddress((void**)&pqkv, g_qkv);
    cudaGetSymbolAddress((void**)&py, g_y);
    cudaGetSymbolAddress((void**)&ph1, g_h1);
    cudaGetSymbolAddress((void**)&ph3, g_h3);
    cudaGetSymbolAddress((void**)&pso, g_so);
    cudaGetSymbolAddress((void**)&pcounts, g_counts);
    cudaGetSymbolAddress((void**)&poffs, g_offs);
    cudaGetSymbolAddress((void**)&pcursor, g_cursor);
    cudaGetSymbolAddress((void**)&pslot_token, g_slot_token);
    cudaGetSymbolAddress((void**)&pslot_w, g_slot_w);
    cudaGetSymbolAddress((void**)&ptoken_slot, g_token_slot);
    cudaGetSymbolAddress((void**)&ptok_e, g_tok_e);
    cudaGetSymbolAddress((void**)&ptok_w, g_tok_w);

    embed_kernel<<<TOK, 256>>>(idx, tok_emb, px);

    for (int l = 0; l < NLAYER; l++) {
        // ---- attention block ----
        rmsnorm_kernel<<<TOK, 256>>>(px, attn_nw + (size_t)l * DMODEL, pxn);
        gemm_bf16_nt<false><<<dim3(QKVN / 128, TOK / 128), 256>>>(
            pxn, wqkv + (size_t)l * QKVN * DMODEL, nullptr, pqkv, QKVN, DMODEL);
        {
            int total = TOK * (NH + NKV) * (HDIM / 2);
            rope_kernel<<<(total + 255) / 256, 256>>>(pqkv);
        }
        flash_kernel<<<dim3(SEQ / 64, NH, NB), 256>>>(pqkv, py);
        gemm_bf16_nt<true><<<dim3(DMODEL / 128, TOK / 128), 256>>>(
            py, wo + (size_t)l * DMODEL * DMODEL, px, px, DMODEL, DMODEL);

        // ---- MoE block ----
        rmsnorm_kernel<<<TOK, 256>>>(px, ffn_nw + (size_t)l * DMODEL, pxn);
        zero_counts_kernel<<<1, 32>>>(pcounts);
        init_slots_kernel<<<(NSLOTP + 255) / 256, 256>>>(pslot_token, pslot_w);
        gate_kernel<<<TOK, 256>>>(pxn, gate_w + (size_t)l * NEXP * DMODEL,
                                  ptok_e, ptok_w, pcounts);
        scan_kernel<<<1, 1>>>(pcounts, poffs, pcursor);
        scatter_kernel<<<(TOK + 255) / 256, 256>>>(ptok_e, ptok_w, pcursor,
                                                   pslot_token, pslot_w, ptoken_slot);
        gemm_bf16_moe<true, false><<<dim3(FFI / 128, NSLOTP / 128, NEXP), 256>>>(
            pxn, w1 + (size_t)l * NEXP * FFI * DMODEL, (long)FFI * DMODEL,
            ph1, FFI, DMODEL, poffs, pslot_token, pslot_w);
        gemm_bf16_moe<true, false><<<dim3(FFI / 128, NSLOTP / 128, NEXP), 256>>>(
            pxn, w3 + (size_t)l * NEXP * FFI * DMODEL, (long)FFI * DMODEL,
            ph3, FFI, DMODEL, poffs, pslot_token, pslot_w);
        {
            long n = (long)NSLOTP * FFI;
            silu_mul_kernel<<<(unsigned)((n + 255) / 256), 256>>>(ph1, ph3);
        }
        gemm_bf16_moe<false, true><<<dim3(DMODEL / 128, NSLOTP / 128, NEXP), 256>>>(
            ph1, w2 + (size_t)l * NEXP * DMODEL * FFI, (long)DMODEL * FFI,
            pso, DMODEL, FFI, poffs, pslot_token, pslot_w);
        combine_kernel<<<TOK, 256>>>(px, pso, ptoken_slot);
    }

    // ---- final norm + LM head ----
    rmsnorm_kernel<<<TOK, 256>>>(px, final_nw, pxn);
    gemm_bf16_nt<false><<<dim3(VOCAB / 128, TOK / 128), 256>>>(
        pxn, out_w, nullptr, logits, VOCAB, DMODEL);
}

// round 4
// speedup vs baseline: 2.4525x; 1.1876x over previous
#include <cuda_runtime.h>
#include <cuda_bf16.h>
#include <mma.h>
#include <math.h>
#include <float.h>

using namespace nvcuda;

// ---------------- problem constants ----------------
#define NB      2
#define SEQ     1024
#define TOK     2048          // NB*SEQ
#define DMODEL  1024
#define NH      16
#define NKV     4
#define HDIM    64
#define NEXP    8
#define TOPK    2
#define NLAYER  2
#define VOCAB   32000
#define FFI     3584
#define QKVN    1536          // (NH + 2*NKV)*HDIM
#define NSLOT   (TOK*TOPK)    // 4096
#define NSLOTP  (NSLOT + NEXP*128)   // 5120

#define BK  32
#define BKP 40                // smem row stride (elems): 80B
#define SMEMB (128*BKP)       // elems per tile array (one buffer)
#define GEMM_SMEM_BYTES (2/*bufs*/ * 4/*arrays*/ * SMEMB * 2/*bytes*/)   // 81920

// ---------------- scratch ----------------
__device__ float g_x  [TOK*DMODEL];
__device__ float g_xn [TOK*DMODEL];
__device__ float g_qkv[TOK*QKVN];
__device__ float g_y  [TOK*DMODEL];
__device__ float g_h1 [NSLOTP*FFI];
__device__ float g_h3 [NSLOTP*FFI];
__device__ float g_so [NSLOTP*DMODEL];
__device__ int   g_counts[NEXP];
__device__ int   g_offs[NEXP+1];
__device__ int   g_cursor[NEXP];
__device__ int   g_slot_token[NSLOTP];
__device__ float g_slot_w[NSLOTP];
__device__ int   g_token_slot[NSLOT];
__device__ int   g_tok_e[TOK*TOPK];
__device__ float g_tok_w[TOK*TOPK];

// ---------------- embedding gather ----------------
__global__ void embed_kernel(const int* __restrict__ idx,
                             const float* __restrict__ emb,
                             float* __restrict__ x) {
    int t = blockIdx.x;
    int row = idx[t];
    const float* src = emb + (size_t)row * DMODEL;
    float* dst = x + (size_t)t * DMODEL;
    for (int d = threadIdx.x; d < DMODEL; d += blockDim.x) dst[d] = src[d];
}

// ---------------- rmsnorm ----------------
__global__ __launch_bounds__(256) void rmsnorm_kernel(const float* __restrict__ x,
                                                      const float* __restrict__ w,
                                                      float* __restrict__ o) {
    int t = blockIdx.x;
    const float* xr = x + (size_t)t * DMODEL;
    float ss = 0.f;
    for (int d = threadIdx.x; d < DMODEL; d += 256) { float v = xr[d]; ss += v * v; }
    for (int off = 16; off; off >>= 1) ss += __shfl_xor_sync(0xffffffffu, ss, off);
    __shared__ float red[8];
    __shared__ float s_inv;
    int warp = threadIdx.x >> 5, lane = threadIdx.x & 31;
    if (lane == 0) red[warp] = ss;
    __syncthreads();
    if (threadIdx.x == 0) {
        float tot = 0.f;
        #pragma unroll
        for (int i = 0; i < 8; i++) tot += red[i];
        s_inv = rsqrtf(tot / (float)DMODEL + 1e-5f);
    }
    __syncthreads();
    float inv = s_inv;
    float* op = o + (size_t)t * DMODEL;
    for (int d = threadIdx.x; d < DMODEL; d += 256) op[d] = xr[d] * inv * w[d];
}

// ---------------- RoPE ----------------
__global__ void rope_kernel(float* __restrict__ qkv) {
    int i = blockIdx.x * blockDim.x + threadIdx.x;
    const int total = TOK * (NH + NKV) * (HDIM / 2);
    if (i >= total) return;
    int pair = i & 31;
    int r = i >> 5;
    int head = r % (NH + NKV);
    int t = r / (NH + NKV);
    int s = t & (SEQ - 1);
    float freq = expf((float)pair * -0.43173470493638357f); // ln(1e6)/32
    float ang = (float)s * freq;
    float sn, c;
    sincosf(ang, &sn, &c);
    float* p = qkv + (size_t)t * QKVN + head * HDIM + 2 * pair;
    float x0 = p[0], x1 = p[1];
    p[0] = x0 * c - x1 * sn;
    p[1] = x1 * c + x0 * sn;
}

// ---------------- split helpers ----------------
__device__ __forceinline__ void split_store4(float4 v, float sc,
                                             __nv_bfloat16* hi, __nv_bfloat16* lo) {
    float f0 = v.x * sc, f1 = v.y * sc, f2 = v.z * sc, f3 = v.w * sc;
    __nv_bfloat162 h01, h23, l01, l23;
    h01.x = __float2bfloat16(f0); h01.y = __float2bfloat16(f1);
    h23.x = __float2bfloat16(f2); h23.y = __float2bfloat16(f3);
    l01.x = __float2bfloat16(f0 - __bfloat162float(h01.x));
    l01.y = __float2bfloat16(f1 - __bfloat162float(h01.y));
    l23.x = __float2bfloat16(f2 - __bfloat162float(h23.x));
    l23.y = __float2bfloat16(f3 - __bfloat162float(h23.y));
    *reinterpret_cast<__nv_bfloat162*>(hi)     = h01;
    *reinterpret_cast<__nv_bfloat162*>(hi + 2) = h23;
    *reinterpret_cast<__nv_bfloat162*>(lo)     = l01;
    *reinterpret_cast<__nv_bfloat162*>(lo + 2) = l23;
}

__device__ __forceinline__ void stage_tiles(__nv_bfloat16* Ah, __nv_bfloat16* Al,
                                            __nv_bfloat16* Bh, __nv_bfloat16* Bl,
                                            int lrow, int lcol,
                                            const float4 va[4], const float4 vb[4],
                                            const float ascale[4]) {
    #pragma unroll
    for (int r = 0; r < 4; r++) {
        int row = r * 32 + lrow;
        split_store4(va[r], ascale[r], Ah + row * BKP + lcol, Al + row * BKP + lcol);
        split_store4(vb[r], 1.f,       Bh + row * BKP + lcol, Bl + row * BKP + lcol);
    }
}

__device__ __forceinline__ void mma_tiles(const __nv_bfloat16* Ah, const __nv_bfloat16* Al,
                                          const __nv_bfloat16* Bh, const __nv_bfloat16* Bl,
                                          int wm, int wn,
                                          wmma::fragment<wmma::accumulator,16,16,16,float> (&acc)[4][2]) {
    #pragma unroll
    for (int ks = 0; ks < BK; ks += 16) {
        wmma::fragment<wmma::matrix_a, 16, 16, 16, __nv_bfloat16, wmma::row_major> ah[4], al[4];
        #pragma unroll
        for (int i = 0; i < 4; i++) {
            wmma::load_matrix_sync(ah[i], Ah + (wm + i * 16) * BKP + ks, BKP);
            wmma::load_matrix_sync(al[i], Al + (wm + i * 16) * BKP + ks, BKP);
        }
        #pragma unroll
        for (int j = 0; j < 2; j++) {
            wmma::fragment<wmma::matrix_b, 16, 16, 16, __nv_bfloat16, wmma::col_major> bf;
            wmma::load_matrix_sync(bf, Bh + (wn + j * 16) * BKP + ks, BKP);
            #pragma unroll
            for (int i = 0; i < 4; i++) wmma::mma_sync(acc[i][j], ah[i], bf, acc[i][j]);
            #pragma unroll
            for (int i = 0; i < 4; i++) wmma::mma_sync(acc[i][j], al[i], bf, acc[i][j]);
            wmma::load_matrix_sync(bf, Bl + (wn + j * 16) * BKP + ks, BKP);
            #pragma unroll
            for (int i = 0; i < 4; i++) wmma::mma_sync(acc[i][j], ah[i], bf, acc[i][j]);
        }
    }
}

// ---------------- pipelined bf16-split GEMM: C = A @ Bw^T (+R) ----------------
template<bool RESID>
__global__ __launch_bounds__(256) void gemm_bf16_nt(const float* __restrict__ A,
                                                    const float* __restrict__ Bw,
                                                    const float* __restrict__ R,
                                                    float* __restrict__ C,
                                                    int N, int K) {
    extern __shared__ __nv_bfloat16 smem_[];
    __nv_bfloat16* Ah = smem_;
    __nv_bfloat16* Al = Ah + 2 * SMEMB;
    __nv_bfloat16* Bh = Al + 2 * SMEMB;
    __nv_bfloat16* Bl = Bh + 2 * SMEMB;

    const int tid = threadIdx.x;
    const int bm = blockIdx.y * 128, bn = blockIdx.x * 128;
    const int lrow = tid >> 3;
    const int lcol = (tid & 7) * 4;
    const int wid = tid >> 5;
    const int wm = (wid & 1) * 64;
    const int wn = (wid >> 1) * 32;
    const float ascale[4] = {1.f, 1.f, 1.f, 1.f};

    wmma::fragment<wmma::accumulator, 16, 16, 16, float> acc[4][2];
    #pragma unroll
    for (int i = 0; i < 4; i++)
        #pragma unroll
        for (int j = 0; j < 2; j++) {
            if (RESID)
                wmma::load_matrix_sync(acc[i][j],
                    R + (size_t)(bm + wm + i * 16) * N + bn + wn + j * 16, N, wmma::mem_row_major);
            else
                wmma::fill_fragment(acc[i][j], 0.f);
        }

    float4 va[4], vb[4];
    #pragma unroll
    for (int r = 0; r < 4; r++) {
        va[r] = *reinterpret_cast<const float4*>(A  + (size_t)(bm + r * 32 + lrow) * K + lcol);
        vb[r] = *reinterpret_cast<const float4*>(Bw + (size_t)(bn + r * 32 + lrow) * K + lcol);
    }
    stage_tiles(Ah, Al, Bh, Bl, lrow, lcol, va, vb, ascale);
    __syncthreads();

    const int nk = K / BK;
    for (int kk = 0; kk < nk; kk++) {
        const int cur = kk & 1;
        if (kk + 1 < nk) {
            const int k0 = (kk + 1) * BK;
            #pragma unroll
            for (int r = 0; r < 4; r++) {
                va[r] = *reinterpret_cast<const float4*>(A  + (size_t)(bm + r * 32 + lrow) * K + k0 + lcol);
                vb[r] = *reinterpret_cast<const float4*>(Bw + (size_t)(bn + r * 32 + lrow) * K + k0 + lcol);
            }
        }
        mma_tiles(Ah + cur * SMEMB, Al + cur * SMEMB, Bh + cur * SMEMB, Bl + cur * SMEMB,
                  wm, wn, acc);
        if (kk + 1 < nk) {
            const int nxt = cur ^ 1;
            stage_tiles(Ah + nxt * SMEMB, Al + nxt * SMEMB, Bh + nxt * SMEMB, Bl + nxt * SMEMB,
                        lrow, lcol, va, vb, ascale);
            __syncthreads();
        }
    }
    #pragma unroll
    for (int i = 0; i < 4; i++)
        #pragma unroll
        for (int j = 0; j < 2; j++)
            wmma::store_matrix_sync(C + (size_t)(bm + wm + i * 16) * N + bn + wn + j * 16,
                                    acc[i][j], N, wmma::mem_row_major);
}

// ---------------- pipelined MoE grouped GEMM ----------------
template<bool GATHER, bool SCALE>
__global__ __launch_bounds__(256) void gemm_bf16_moe(const float* __restrict__ X,
                                                     const float* __restrict__ Wbase,
                                                     long wstride,
                                                     float* __restrict__ C,
                                                     int N, int K,
                                                     const int* __restrict__ offs,
                                                     const int* __restrict__ slot_token,
                                                     const float* __restrict__ slot_w) {
    const int e = blockIdx.z;
    const int row0 = offs[e] + blockIdx.y * 128;
    if (row0 >= offs[e + 1]) return;
    const float* W = Wbase + (long)e * wstride;

    extern __shared__ __nv_bfloat16 smem_[];
    __nv_bfloat16* Ah = smem_;
    __nv_bfloat16* Al = Ah + 2 * SMEMB;
    __nv_bfloat16* Bh = Al + 2 * SMEMB;
    __nv_bfloat16* Bl = Bh + 2 * SMEMB;

    const int tid = threadIdx.x;
    const int bn = blockIdx.x * 128;
    const int lrow = tid >> 3;
    const int lcol = (tid & 7) * 4;
    const int wid = tid >> 5;
    const int wm = (wid & 1) * 64;
    const int wn = (wid >> 1) * 32;

    const float* aptr[4];
    float ascale[4];
    #pragma unroll
    for (int r = 0; r < 4; r++) {
        int grow = row0 + r * 32 + lrow;
        if (GATHER) {
            aptr[r] = X + (size_t)slot_token[grow] * K;
            ascale[r] = 1.f;
        } else {
            aptr[r] = X + (size_t)grow * K;
            ascale[r] = SCALE ? slot_w[grow] : 1.f;
        }
    }

    wmma::fragment<wmma::accumulator, 16, 16, 16, float> acc[4][2];
    #pragma unroll
    for (int i = 0; i < 4; i++)
        #pragma unroll
        for (int j = 0; j < 2; j++) wmma::fill_fragment(acc[i][j], 0.f);

    float4 va[4], vb[4];
    #pragma unroll
    for (int r = 0; r < 4; r++) {
        va[r] = *reinterpret_cast<const float4*>(aptr[r] + lcol);
        vb[r] = *reinterpret_cast<const float4*>(W + (size_t)(bn + r * 32 + lrow) * K + lcol);
    }
    stage_tiles(Ah, Al, Bh, Bl, lrow, lcol, va, vb, ascale);
    __syncthreads();

    const int nk = K / BK;
    for (int kk = 0; kk < nk; kk++) {
        const int cur = kk & 1;
        if (kk + 1 < nk) {
            const int k0 = (kk + 1) * BK;
            #pragma unroll
            for (int r = 0; r < 4; r++) {
                va[r] = *reinterpret_cast<const float4*>(aptr[r] + k0 + lcol);
                vb[r] = *reinterpret_cast<const float4*>(W + (size_t)(bn + r * 32 + lrow) * K + k0 + lcol);
            }
        }
        mma_tiles(Ah + cur * SMEMB, Al + cur * SMEMB, Bh + cur * SMEMB, Bl + cur * SMEMB,
                  wm, wn, acc);
        if (kk + 1 < nk) {
            const int nxt = cur ^ 1;
            stage_tiles(Ah + nxt * SMEMB, Al + nxt * SMEMB, Bh + nxt * SMEMB, Bl + nxt * SMEMB,
                        lrow, lcol, va, vb, ascale);
            __syncthreads();
        }
    }
    #pragma unroll
    for (int i = 0; i < 4; i++)
        #pragma unroll
        for (int j = 0; j < 2; j++)
            wmma::store_matrix_sync(C + (size_t)(row0 + wm + i * 16) * N + bn + wn + j * 16,
                                    acc[i][j], N, wmma::mem_row_major);
}

// ---------------- flash attention (fp32, 64x64 tiles) ----------------
__global__ __launch_bounds__(256) void flash_kernel(const float* __restrict__ qkv,
                                                    float* __restrict__ y) {
    __shared__ float Qs[64][64];
    __shared__ float Ks[64][64];
    __shared__ float Vs[64][64];
    const int b = blockIdx.z, h = blockIdx.y;
    const int q0 = blockIdx.x * 64;
    const int kvh = h >> 2;
    const int tid = threadIdx.x;
    const int tx = tid & 15, ty = tid >> 4;
    const int lr = tid >> 2;
    const int lc = (tid & 3) * 16;

    {
        const float* qp = qkv + (size_t)(b * SEQ + q0 + lr) * QKVN + h * HDIM + lc;
        #pragma unroll
        for (int j = 0; j < 4; j++)
            *reinterpret_cast<float4*>(&Qs[lr][lc + j * 4]) =
                *reinterpret_cast<const float4*>(qp + j * 4);
    }

    float m[4], l[4], O[4][4];
    #pragma unroll
    for (int i = 0; i < 4; i++) {
        m[i] = -FLT_MAX; l[i] = 0.f;
        #pragma unroll
        for (int j = 0; j < 4; j++) O[i][j] = 0.f;
    }

    const int ntile = q0 / 64 + 1;
    for (int kt = 0; kt < ntile; kt++) {
        const int k0 = kt * 64;
        __syncthreads();
        {
            const float* kp = qkv + (size_t)(b * SEQ + k0 + lr) * QKVN + DMODEL + kvh * HDIM + lc;
            const float* vp = qkv + (size_t)(b * SEQ + k0 + lr) * QKVN + DMODEL + NKV * HDIM + kvh * HDIM + lc;
            #pragma unroll
            for (int j = 0; j < 4; j++) {
                float4 kv = *reinterpret_cast<const float4*>(kp + j * 4);
                Ks[lc + j * 4 + 0][lr] = kv.x;
                Ks[lc + j * 4 + 1][lr] = kv.y;
                Ks[lc + j * 4 + 2][lr] = kv.z;
                Ks[lc + j * 4 + 3][lr] = kv.w;
                *reinterpret_cast<float4*>(&Vs[lr][lc + j * 4]) =
                    *reinterpret_cast<const float4*>(vp + j * 4);
            }
        }
        __syncthreads();

        float s[4][4];
        #pragma unroll
        for (int i = 0; i < 4; i++)
            #pragma unroll
            for (int j = 0; j < 4; j++) s[i][j] = 0.f;
        for (int d = 0; d < 64; d++) {
            float4 kd = *reinterpret_cast<const float4*>(&Ks[d][tx * 4]);
            #pragma unroll
            for (int i = 0; i < 4; i++) {
                float qv = Qs[ty * 4 + i][d];
                s[i][0] += qv * kd.x; s[i][1] += qv * kd.y;
                s[i][2] += qv * kd.z; s[i][3] += qv * kd.w;
            }
        }

        #pragma unroll
        for (int i = 0; i < 4; i++) {
            int qg = q0 + ty * 4 + i;
            float rm = -FLT_MAX;
            #pragma unroll
            for (int j = 0; j < 4; j++) {
                int kg = k0 + tx * 4 + j;
                float v = (kg <= qg) ? s[i][j] * 0.125f : -FLT_MAX;
                s[i][j] = v;
                rm = fmaxf(rm, v);
            }
            for (int off = 8; off; off >>= 1)
                rm = fmaxf(rm, __shfl_xor_sync(0xffffffffu, rm, off, 16));
            float mn = fmaxf(m[i], rm);
            float corr = __expf(m[i] - mn);
            float rs = 0.f;
            #pragma unroll
            for (int j = 0; j < 4; j++) {
                float p = __expf(s[i][j] - mn);
                s[i][j] = p; rs += p;
            }
            for (int off = 8; off; off >>= 1)
                rs += __shfl_xor_sync(0xffffffffu, rs, off, 16);
            l[i] = l[i] * corr + rs;
            m[i] = mn;
            #pragma unroll
            for (int j = 0; j < 4; j++) O[i][j] *= corr;
        }
        __syncthreads();
        #pragma unroll
        for (int i = 0; i < 4; i++)
            #pragma unroll
            for (int j = 0; j < 4; j++) Ks[ty * 4 + i][tx * 4 + j] = s[i][j];
        __syncthreads();
        for (int c = 0; c < 64; c++) {
            float4 vv = *reinterpret_cast<const float4*>(&Vs[c][tx * 4]);
            #pragma unroll
            for (int i = 0; i < 4; i++) {
                float p = Ks[ty * 4 + i][c];
                O[i][0] += p * vv.x; O[i][1] += p * vv.y;
                O[i][2] += p * vv.z; O[i][3] += p * vv.w;
            }
        }
    }
    #pragma unroll
    for (int i = 0; i < 4; i++) {
        float inv = 1.f / l[i];
        #pragma unroll
        for (int j = 0; j < 4; j++)
            y[(size_t)(b * SEQ + q0 + ty * 4 + i) * DMODEL + h * HDIM + tx * 4 + j] = O[i][j] * inv;
    }
}

// ---------------- MoE routing ----------------
__global__ void zero_counts_kernel(int* counts) {
    if (threadIdx.x < NEXP) counts[threadIdx.x] = 0;
}

__global__ void init_slots_kernel(int* slot_token, float* slot_w) {
    int i = blockIdx.x * blockDim.x + threadIdx.x;
    if (i < NSLOTP) { slot_token[i] = 0; slot_w[i] = 0.f; }
}

__global__ __launch_bounds__(256) void gate_kernel(const float* __restrict__ xn,
                                                   const float* __restrict__ gw,
                                                   int* __restrict__ tok_e,
                                                   float* __restrict__ tok_w,
                                                   int* __restrict__ counts) {
    int t = blockIdx.x;
    int w = threadIdx.x >> 5, lane = threadIdx.x & 31;
    __shared__ float sc[NEXP];
    const float* x = xn + (size_t)t * DMODEL;
    const float* g = gw + (size_t)w * DMODEL;
    float s = 0.f;
    for (int d = lane; d < DMODEL; d += 32) s += x[d] * g[d];
    for (int off = 16; off; off >>= 1) s += __shfl_xor_sync(0xffffffffu, s, off);
    if (lane == 0) sc[w] = s;
    __syncthreads();
    if (threadIdx.x == 0) {
        float mx = sc[0];
        #pragma unroll
        for (int e = 1; e < NEXP; e++) mx = fmaxf(mx, sc[e]);
        float p[NEXP], sum = 0.f;
        #pragma unroll
        for (int e = 0; e < NEXP; e++) { p[e] = __expf(sc[e] - mx); sum += p[e]; }
        int i0 = 0;
        #pragma unroll
        for (int e = 1; e < NEXP; e++) if (p[e] > p[i0]) i0 = e;
        int i1 = (i0 == 0) ? 1 : 0;
        #pragma unroll
        for (int e = 0; e < NEXP; e++) if (e != i0 && p[e] > p[i1]) i1 = e;
        float v0 = p[i0] / sum, v1 = p[i1] / sum;
        float inv = 1.f / (v0 + v1);
        tok_e[2 * t] = i0;  tok_e[2 * t + 1] = i1;
        tok_w[2 * t] = v0 * inv; tok_w[2 * t + 1] = v1 * inv;
        atomicAdd(&counts[i0], 1); atomicAdd(&counts[i1], 1);
    }
}

__global__ void scan_kernel(const int* __restrict__ counts, int* __restrict__ offs,
                            int* __restrict__ cursor) {
    if (threadIdx.x == 0) {
        int acc = 0;
        for (int e = 0; e < NEXP; e++) {
            offs[e] = acc; cursor[e] = acc;
            acc += ((counts[e] + 127) >> 7) << 7;
        }
        offs[NEXP] = acc;
    }
}

__global__ void scatter_kernel(const int* __restrict__ tok_e, const float* __restrict__ tok_w,
                               int* __restrict__ cursor, int* __restrict__ slot_token,
                               float* __restrict__ slot_w, int* __restrict__ token_slot) {
    int t = blockIdx.x * blockDim.x + threadIdx.x;
    if (t >= TOK) return;
    #pragma unroll
    for (int j = 0; j < TOPK; j++) {
        int e = tok_e[2 * t + j];
        int slot = atomicAdd(&cursor[e], 1);
        slot_token[slot] = t;
        slot_w[slot] = tok_w[2 * t + j];
        token_slot[2 * t + j] = slot;
    }
}

__global__ void silu_mul_kernel(float* __restrict__ h1, const float* __restrict__ h3) {
    long i = (long)blockIdx.x * blockDim.x + threadIdx.x;
    if (i < (long)NSLOTP * FFI) {
        float a = h1[i];
        h1[i] = (a / (1.f + __expf(-a))) * h3[i];
    }
}

__global__ void combine_kernel(float* __restrict__ x, const float* __restrict__ so,
                               const int* __restrict__ token_slot) {
    int t = blockIdx.x;
    int s0 = token_slot[2 * t], s1 = token_slot[2 * t + 1];
    float* xp = x + (size_t)t * DMODEL;
    const float* a = so + (size_t)s0 * DMODEL;
    const float* b = so + (size_t)s1 * DMODEL;
    for (int d = threadIdx.x; d < DMODEL; d += blockDim.x) xp[d] += a[d] + b[d];
}

// ---------------- orchestration ----------------
extern "C" void kernel_launch(void* const* d_in, const int* in_sizes, int n_in,
                              void* d_out, int out_size) {
    const int*   idx      = (const int*)  d_in[0];
    const float* tok_emb  = (const float*)d_in[1];
    const float* attn_nw  = (const float*)d_in[2];
    const float* wqkv     = (const float*)d_in[3];
    const float* wo       = (const float*)d_in[4];
    const float* ffn_nw   = (const float*)d_in[5];
    const float* gate_w   = (const float*)d_in[6];
    const float* w1       = (const float*)d_in[7];
    const float* w2       = (const float*)d_in[8];
    const float* w3       = (const float*)d_in[9];
    const float* final_nw = (const float*)d_in[10];
    const float* out_w    = (const float*)d_in[11];
    float* logits = (float*)d_out;

    // Idempotent, host-side, non-stream ops: safe under graph capture, run every call.
    cudaFuncSetAttribute(gemm_bf16_nt<false>,
        cudaFuncAttributeMaxDynamicSharedMemorySize, GEMM_SMEM_BYTES);
    cudaFuncSetAttribute(gemm_bf16_nt<true>,
        cudaFuncAttributeMaxDynamicSharedMemorySize, GEMM_SMEM_BYTES);
    cudaFuncSetAttribute(gemm_bf16_moe<true, false>,
        cudaFuncAttributeMaxDynamicSharedMemorySize, GEMM_SMEM_BYTES);
    cudaFuncSetAttribute(gemm_bf16_moe<false, true>,
        cudaFuncAttributeMaxDynamicSharedMemorySize, GEMM_SMEM_BYTES);

    float *px, *pxn, *pqkv, *py, *ph1, *ph3, *pso, *pslot_w, *ptok_w;
    int *pcounts, *poffs, *pcursor, *pslot_token, *ptoken_slot, *ptok_e;
    cudaGetSymbolAddress((void**)&px, g_x);
    cudaGetSymbolAddress((void**)&pxn, g_xn);
    cudaGetSymbolAddress((void**)&pqkv, g_qkv);
    cudaGetSymbolAddress((void**)&py, g_y);
    cudaGetSymbolAddress((void**)&ph1, g_h1);
    cudaGetSymbolAddress((void**)&ph3, g_h3);
    cudaGetSymbolAddress((void**)&pso, g_so);
    cudaGetSymbolAddress((void**)&pcounts, g_counts);
    cudaGetSymbolAddress((void**)&poffs, g_offs);
    cudaGetSymbolAddress((void**)&pcursor, g_cursor);
    cudaGetSymbolAddress((void**)&pslot_token, g_slot_token);
    cudaGetSymbolAddress((void**)&pslot_w, g_slot_w);
    cudaGetSymbolAddress((void**)&ptoken_slot, g_token_slot);
    cudaGetSymbolAddress((void**)&ptok_e, g_tok_e);
    cudaGetSymbolAddress((void**)&ptok_w, g_tok_w);

    embed_kernel<<<TOK, 256>>>(idx, tok_emb, px);

    for (int l = 0; l < NLAYER; l++) {
        // ---- attention block ----
        rmsnorm_kernel<<<TOK, 256>>>(px, attn_nw + (size_t)l * DMODEL, pxn);
        gemm_bf16_nt<false><<<dim3(QKVN / 128, TOK / 128), 256, GEMM_SMEM_BYTES>>>(
            pxn, wqkv + (size_t)l * QKVN * DMODEL, nullptr, pqkv, QKVN, DMODEL);
        {
            int total = TOK * (NH + NKV) * (HDIM / 2);
            rope_kernel<<<(total + 255) / 256, 256>>>(pqkv);
        }
        flash_kernel<<<dim3(SEQ / 64, NH, NB), 256>>>(pqkv, py);
        gemm_bf16_nt<true><<<dim3(DMODEL / 128, TOK / 128), 256, GEMM_SMEM_BYTES>>>(
            py, wo + (size_t)l * DMODEL * DMODEL, px, px, DMODEL, DMODEL);

        // ---- MoE block ----
        rmsnorm_kernel<<<TOK, 256>>>(px, ffn_nw + (size_t)l * DMODEL, pxn);
        zero_counts_kernel<<<1, 32>>>(pcounts);
        init_slots_kernel<<<(NSLOTP + 255) / 256, 256>>>(pslot_token, pslot_w);
        gate_kernel<<<TOK, 256>>>(pxn, gate_w + (size_t)l * NEXP * DMODEL,
                                  ptok_e, ptok_w, pcounts);
        scan_kernel<<<1, 1>>>(pcounts, poffs, pcursor);
        scatter_kernel<<<(TOK + 255) / 256, 256>>>(ptok_e, ptok_w, pcursor,
                                                   pslot_token, pslot_w, ptoken_slot);
        gemm_bf16_moe<true, false><<<dim3(FFI / 128, NSLOTP / 128, NEXP), 256, GEMM_SMEM_BYTES>>>(
            pxn, w1 + (size_t)l * NEXP * FFI * DMODEL, (long)FFI * DMODEL,
            ph1, FFI, DMODEL, poffs, pslot_token, pslot_w);
        gemm_bf16_moe<true, false><<<dim3(FFI / 128, NSLOTP / 128, NEXP), 256, GEMM_SMEM_BYTES>>>(
            pxn, w3 + (size_t)l * NEXP * FFI * DMODEL, (long)FFI * DMODEL,
            ph3, FFI, DMODEL, poffs, pslot_token, pslot_w);
        {
            long n = (long)NSLOTP * FFI;
            silu_mul_kernel<<<(unsigned)((n + 255) / 256), 256>>>(ph1, ph3);
        }
        gemm_bf16_moe<false, true><<<dim3(DMODEL / 128, NSLOTP / 128, NEXP), 256, GEMM_SMEM_BYTES>>>(
            ph1, w2 + (size_t)l * NEXP * DMODEL * FFI, (long)DMODEL * FFI,
            pso, DMODEL, FFI, poffs, pslot_token, pslot_w);
        combine_kernel<<<TOK, 256>>>(px, pso, ptoken_slot);
    }

    // ---- final norm + LM head ----
    rmsnorm_kernel<<<TOK, 256>>>(px, final_nw, pxn);
    gemm_bf16_nt<false><<<dim3(VOCAB / 128, TOK / 128), 256, GEMM_SMEM_BYTES>>>(
        pxn, out_w, nullptr, logits, VOCAB, DMODEL);
}